// round 1
// baseline (speedup 1.0000x reference)
#include <cuda_runtime.h>

// EdgeNetwork factored:
//   T[a][k][i]  = sum_j K[k][i*16+j] * A[a][j]     (precompute per atom)
//   Tb[a][i]    = sum_j bias[i*16+j] * A[a][j]
//   msg[e][i]   = sum_k b[e][k] * T[nb_e][k][i] + Tb[nb_e][i]
//   out[dst_e]  += msg[e]   (atomics)

#define MAX_ATOMS 20000
#define MAX_EDGES 640000

__device__ float g_T[MAX_ATOMS * 256];   // [a][k][i], i fastest
__device__ float g_Tb[MAX_ATOMS * 16];   // [a][i]

// One block (256 threads) handles 16 atoms. thread = (k = tid>>4, i = tid&15).
__global__ void precompute_T(const float* __restrict__ A,
                             const float* __restrict__ Kmat,
                             const float* __restrict__ bias,
                             int n_atoms) {
    __shared__ float Ks[16 * 256];
    __shared__ float Bs[256];
    __shared__ float As[16 * 16];

    const int tid = threadIdx.x;  // 256 threads
    #pragma unroll
    for (int r = 0; r < 16; ++r)
        Ks[r * 256 + tid] = Kmat[r * 256 + tid];
    Bs[tid] = bias[tid];

    const int a0 = blockIdx.x * 16;
    {
        int idx = a0 * 16 + tid;
        As[tid] = (idx < n_atoms * 16) ? A[idx] : 0.f;
    }
    __syncthreads();

    const int k = tid >> 4;
    const int i = tid & 15;

    float kv[16];
    #pragma unroll
    for (int j = 0; j < 16; ++j)
        kv[j] = Ks[k * 256 + i * 16 + j];

    #pragma unroll
    for (int la = 0; la < 16; ++la) {
        int a = a0 + la;
        if (a >= n_atoms) break;
        float s = 0.f;
        #pragma unroll
        for (int j = 0; j < 16; ++j)
            s += kv[j] * As[la * 16 + j];
        g_T[(size_t)a * 256 + tid] = s;  // coalesced: a*256 + k*16 + i
    }

    if (tid < 16) {  // i = tid: bias term
        #pragma unroll
        for (int la = 0; la < 16; ++la) {
            int a = a0 + la;
            if (a >= n_atoms) break;
            float s = 0.f;
            #pragma unroll
            for (int j = 0; j < 16; ++j)
                s += Bs[tid * 16 + j] * As[la * 16 + j];
            g_Tb[a * 16 + tid] = s;
        }
    }
}

// 4 threads per edge; thread t handles msg[i] for i = 4t .. 4t+3.
__global__ void edge_msgs(const float* __restrict__ bond,
                          const int* __restrict__ pairs,
                          float* __restrict__ out,
                          int n_edges) {
    const int gid = blockIdx.x * blockDim.x + threadIdx.x;
    const int e = gid >> 2;
    const int t = gid & 3;
    const bool valid = (e < n_edges);
    const int ec = valid ? e : (n_edges - 1);  // keep all lanes active for shfl

    const int dst = pairs[2 * ec];
    const int nb  = pairs[2 * ec + 1];

    // this thread's 4 bond features: b[e][4t .. 4t+3]
    const float4 bv = reinterpret_cast<const float4*>(bond)[ec * 4 + t];
    float bcomp[4] = {bv.x, bv.y, bv.z, bv.w};

    // init accumulators with bias term Tb[nb][4t..4t+3]
    float4 acc = reinterpret_cast<const float4*>(g_Tb)[nb * 4 + t];

    const float4* Trow = reinterpret_cast<const float4*>(g_T + (size_t)nb * 256);
    #pragma unroll
    for (int k = 0; k < 16; ++k) {
        // b[e][k] lives in sub-lane (k>>2), component (k&3) of this 4-group
        float bk = __shfl_sync(0xffffffffu, bcomp[k & 3], k >> 2, 4);
        float4 tv = Trow[k * 4 + t];  // T[nb][k][4t..4t+3], 64B coalesced per group
        acc.x += bk * tv.x;
        acc.y += bk * tv.y;
        acc.z += bk * tv.z;
        acc.w += bk * tv.w;
    }

    if (valid) {
        float* o = out + dst * 16 + 4 * t;
        atomicAdd(o + 0, acc.x);
        atomicAdd(o + 1, acc.y);
        atomicAdd(o + 2, acc.z);
        atomicAdd(o + 3, acc.w);
    }
}

extern "C" void kernel_launch(void* const* d_in, const int* in_sizes, int n_in,
                              void* d_out, int out_size) {
    const float* A     = (const float*)d_in[0];  // atom_features [n_atoms,16]
    const float* bond  = (const float*)d_in[1];  // bond_features [n_edges,16]
    const int*   pairs = (const int*)  d_in[2];  // pair_indices  [n_edges,2]
    const float* Kmat  = (const float*)d_in[3];  // kernel [16,256]
    const float* bias  = (const float*)d_in[4];  // bias [256]
    float* out = (float*)d_out;                  // [n_atoms,16]

    const int n_atoms = in_sizes[0] / 16;
    const int n_edges = in_sizes[2] / 2;

    // output is accumulated via atomics — zero it first (graph-capturable memset)
    cudaMemsetAsync(out, 0, (size_t)out_size * sizeof(float), 0);

    // Phase 1: per-atom precompute T, Tb
    {
        int blocks = (n_atoms + 15) / 16;
        precompute_T<<<blocks, 256>>>(A, Kmat, bias, n_atoms);
    }

    // Phase 2: per-edge contraction + scatter-add
    {
        long long total_threads = (long long)n_edges * 4;
        int blocks = (int)((total_threads + 255) / 256);
        edge_msgs<<<blocks, 256>>>(bond, pairs, out, n_edges);
    }
}

// round 2
// speedup vs baseline: 1.2777x; 1.2777x over previous
#include <cuda_runtime.h>

// EdgeNetwork factored:
//   T[a][k][i]  = sum_j K[k][i*16+j] * A[a][j]     (precompute per atom)
//   Tb[a][i]    = sum_j bias[i*16+j] * A[a][j]
//   msg[e][i]   = sum_k b[e][k] * T[nb_e][k][i] + Tb[nb_e][i]
//   out[dst_e]  += msg[e]   (vector red atomics)

#define MAX_ATOMS 20000

__device__ float g_T[MAX_ATOMS * 256];   // [a][k][i], i fastest
__device__ float g_Tb[MAX_ATOMS * 16];   // [a][i]

__device__ __forceinline__ void red_add_v4(float* addr, float4 v) {
    asm volatile("red.global.add.v4.f32 [%0], {%1,%2,%3,%4};"
                 :: "l"(addr), "f"(v.x), "f"(v.y), "f"(v.z), "f"(v.w)
                 : "memory");
}

// One block (256 threads) handles 16 atoms. thread = (k = tid>>4, i = tid&15).
__global__ void precompute_T(const float* __restrict__ A,
                             const float* __restrict__ Kmat,
                             const float* __restrict__ bias,
                             int n_atoms) {
    __shared__ float Ks[16 * 256];
    __shared__ float Bs[256];
    __shared__ float As[16 * 16];

    const int tid = threadIdx.x;  // 256 threads
    #pragma unroll
    for (int r = 0; r < 16; ++r)
        Ks[r * 256 + tid] = Kmat[r * 256 + tid];
    Bs[tid] = bias[tid];

    const int a0 = blockIdx.x * 16;
    {
        int idx = a0 * 16 + tid;
        As[tid] = (idx < n_atoms * 16) ? A[idx] : 0.f;
    }
    __syncthreads();

    const int k = tid >> 4;
    const int i = tid & 15;

    float kv[16];
    #pragma unroll
    for (int j = 0; j < 16; ++j)
        kv[j] = Ks[k * 256 + i * 16 + j];

    #pragma unroll
    for (int la = 0; la < 16; ++la) {
        int a = a0 + la;
        if (a >= n_atoms) break;
        float s = 0.f;
        #pragma unroll
        for (int j = 0; j < 16; ++j)
            s += kv[j] * As[la * 16 + j];
        g_T[(size_t)a * 256 + tid] = s;  // coalesced: a*256 + k*16 + i
    }

    if (tid < 16) {  // i = tid: bias term
        #pragma unroll
        for (int la = 0; la < 16; ++la) {
            int a = a0 + la;
            if (a >= n_atoms) break;
            float s = 0.f;
            #pragma unroll
            for (int j = 0; j < 16; ++j)
                s += Bs[tid * 16 + j] * As[la * 16 + j];
            g_Tb[a * 16 + tid] = s;
        }
    }
}

// 8 threads per edge (warp = 4 edges).
// Iteration k2 in [0,8): the 8-lane group loads T[nb][2k2..2k2+1][0..15]
// = 128 contiguous bytes in ONE wavefront (lane t -> float4 at floats k2*32+4t).
//   lanes 0..3 accumulate k=2k2   for i = 4t..4t+3   (coeff b[e][2k2])
//   lanes 4..7 accumulate k=2k2+1 for i = 4(t-4)..   (coeff b[e][2k2+1])
// Final: acc += shfl_xor(acc, 4); lanes 0..3 hold msg[i], emitted with red.v4.
__global__ void edge_msgs(const float* __restrict__ bond,
                          const int* __restrict__ pairs,
                          float* __restrict__ out,
                          int n_edges) {
    const int gid = blockIdx.x * blockDim.x + threadIdx.x;
    const int e = gid >> 3;
    const int t = gid & 7;
    const bool valid = (e < n_edges);
    const int ec = valid ? e : (n_edges - 1);  // keep lanes active for shfl

    const int2 pr = reinterpret_cast<const int2*>(pairs)[ec];
    const int dst = pr.x;
    const int nb  = pr.y;

    // this thread's 2 bond features: b[e][2t], b[e][2t+1]
    const float2 bv = reinterpret_cast<const float2*>(bond)[ec * 8 + t];

    float4 acc;
    if (t < 4) {
        acc = reinterpret_cast<const float4*>(g_Tb)[nb * 4 + t];  // bias term
    } else {
        acc = make_float4(0.f, 0.f, 0.f, 0.f);
    }

    const float4* Trow = reinterpret_cast<const float4*>(g_T + (size_t)nb * 256);
    #pragma unroll
    for (int k2 = 0; k2 < 8; ++k2) {
        const float b_lo = __shfl_sync(0xffffffffu, bv.x, k2, 8);
        const float b_hi = __shfl_sync(0xffffffffu, bv.y, k2, 8);
        const float bk = (t < 4) ? b_lo : b_hi;
        const float4 tv = Trow[k2 * 8 + t];  // 128B/group/iter, single wavefront
        acc.x += bk * tv.x;
        acc.y += bk * tv.y;
        acc.z += bk * tv.z;
        acc.w += bk * tv.w;
    }

    // combine the two k-parities (lane t ^ 4 stays inside the 8-aligned group)
    acc.x += __shfl_xor_sync(0xffffffffu, acc.x, 4);
    acc.y += __shfl_xor_sync(0xffffffffu, acc.y, 4);
    acc.z += __shfl_xor_sync(0xffffffffu, acc.z, 4);
    acc.w += __shfl_xor_sync(0xffffffffu, acc.w, 4);

    if (valid && t < 4) {
        red_add_v4(out + dst * 16 + 4 * t, acc);  // one vector red per lane
    }
}

extern "C" void kernel_launch(void* const* d_in, const int* in_sizes, int n_in,
                              void* d_out, int out_size) {
    const float* A     = (const float*)d_in[0];  // atom_features [n_atoms,16]
    const float* bond  = (const float*)d_in[1];  // bond_features [n_edges,16]
    const int*   pairs = (const int*)  d_in[2];  // pair_indices  [n_edges,2]
    const float* Kmat  = (const float*)d_in[3];  // kernel [16,256]
    const float* bias  = (const float*)d_in[4];  // bias [256]
    float* out = (float*)d_out;                  // [n_atoms,16]

    const int n_atoms = in_sizes[0] / 16;
    const int n_edges = in_sizes[2] / 2;

    // output is accumulated via atomics — zero it first (graph-capturable memset)
    cudaMemsetAsync(out, 0, (size_t)out_size * sizeof(float), 0);

    // Phase 1: per-atom precompute T, Tb
    {
        int blocks = (n_atoms + 15) / 16;
        precompute_T<<<blocks, 256>>>(A, Kmat, bias, n_atoms);
    }

    // Phase 2: per-edge contraction + scatter-add (8 threads/edge)
    {
        long long total_threads = (long long)n_edges * 8;
        int blocks = (int)((total_threads + 255) / 256);
        edge_msgs<<<blocks, 256>>>(bond, pairs, out, n_edges);
    }
}